// round 16
// baseline (speedup 1.0000x reference)
#include <cuda_runtime.h>
#include <cuda_fp16.h>
#include <math.h>
#include <cstdint>

// Problem constants
#define BB    4
#define NTOK  32768          // B*N
#define CC    256
#define HH    8
#define HD    32
#define LL    64
#define NBLK  512            // B * NB
#define EGH   16

// ---------------- scratch (device globals; no allocs allowed) ----------------
__device__ float  g_q  [(size_t)NTOK * CC];            // Q raw fp32
__device__ float  g_khi[(size_t)NTOK * CC];            // K tf32-hi
__device__ float  g_klo[(size_t)NTOK * CC];            // K tf32-lo
__device__ float  g_v  [(size_t)NTOK * CC];            // V tf32
__device__ float  g_xc[(size_t)NTOK * CC];             // x pre-rounded to tf32
__device__ float  g_wc[(size_t)(768 + 256) * CC];      // qkv_w | proj_w, tf32-rounded
__device__ __half g_gateh[(size_t)NBLK * 8 * 64 * 64]; // [blk][h][q][k] fp16
__device__ float  g_bias[(size_t)NBLK * 64 * 64];      // [blk][q][k] bias or -1e30
__device__ float  g_xm[(size_t)NTOK * CC];             // attn out (tf32-rounded)

// ======================= PTX helpers =======================
__device__ __forceinline__ uint32_t smem_to_u32(const void* p) {
    uint32_t a;
    asm("{ .reg .u64 t; cvta.to.shared.u64 t, %1; cvt.u32.u64 %0, t; }"
        : "=r"(a) : "l"(p));
    return a;
}

__device__ __forceinline__ void cp_async16(uint32_t smem_addr, const void* gptr) {
    asm volatile("cp.async.cg.shared.global [%0], [%1], 16;"
                 :: "r"(smem_addr), "l"(gptr));
}
#define CP_COMMIT() asm volatile("cp.async.commit_group;" ::: "memory")
#define CP_WAIT(n)  asm volatile("cp.async.wait_group %0;" :: "n"(n) : "memory")

__device__ __forceinline__ void ldsm4(uint32_t& r0, uint32_t& r1, uint32_t& r2,
                                      uint32_t& r3, uint32_t addr) {
    asm volatile("ldmatrix.sync.aligned.m8n8.x4.shared.b16 {%0,%1,%2,%3}, [%4];"
                 : "=r"(r0), "=r"(r1), "=r"(r2), "=r"(r3) : "r"(addr));
}

__device__ __forceinline__ uint32_t to_tf32(uint32_t x) {
    uint32_t y;
    asm("cvt.rna.tf32.f32 %0, %1;" : "=r"(y) : "r"(x));
    return y;
}

__device__ __forceinline__ float to_tf32f(float x) {
    return __uint_as_float(to_tf32(__float_as_uint(x)));
}

__device__ __forceinline__ void split_tf32(uint32_t x, uint32_t& hi, uint32_t& lo) {
    hi = to_tf32(x);
    float r = __uint_as_float(x) - __uint_as_float(hi);
    lo = to_tf32(__float_as_uint(r));
}

__device__ __forceinline__ void mma_tf32(float& c0, float& c1, float& c2, float& c3,
                                         uint32_t a0, uint32_t a1, uint32_t a2, uint32_t a3,
                                         uint32_t b0, uint32_t b1) {
    asm volatile(
        "mma.sync.aligned.m16n8k8.row.col.f32.tf32.tf32.f32 "
        "{%0,%1,%2,%3}, {%4,%5,%6,%7}, {%8,%9}, {%0,%1,%2,%3};"
        : "+f"(c0), "+f"(c1), "+f"(c2), "+f"(c3)
        : "r"(a0), "r"(a1), "r"(a2), "r"(a3), "r"(b0), "r"(b1));
}

// fast erf: Abramowitz-Stegun 7.1.26, |abs err| <= 1.5e-7
__device__ __forceinline__ float erf_fast(float x) {
    float ax = fabsf(x);
    float t = __frcp_rn(fmaf(0.3275911f, ax, 1.0f));
    float y = t * fmaf(t, fmaf(t, fmaf(t, fmaf(t, 1.061405429f, -1.453152027f),
                                       1.421413741f), -0.284496736f), 0.254829592f);
    float r = 1.0f - y * __expf(-ax * ax);
    return copysignf(r, x);
}

// ---------------- merged tf32 pre-round pass (x | qkv_w | proj_w) ----------------
#define N4X  (NTOK * CC / 4)
#define N4W1 (768 * CC / 4)
#define N4W2 (CC * CC / 4)
#define N4ALL (N4X + N4W1 + N4W2)

__global__ __launch_bounds__(256) void cvt_all_k(
    const float4* __restrict__ x, const float4* __restrict__ w1,
    const float4* __restrict__ w2, float4* __restrict__ xc,
    float4* __restrict__ wc)
{
    int i = blockIdx.x * blockDim.x + threadIdx.x;
    if (i >= N4ALL) return;
    const float4* s;
    float4* d;
    if (i < N4X)              { s = x + i;               d = xc + i; }
    else if (i < N4X + N4W1)  { int j = i - N4X;         s = w1 + j; d = wc + j; }
    else                      { int j = i - N4X - N4W1;  s = w2 + j; d = wc + N4W1 + j; }
    float4 v = *s;
    v.x = to_tf32f(v.x); v.y = to_tf32f(v.y);
    v.z = to_tf32f(v.z); v.w = to_tf32f(v.w);
    *d = v;
}

// ============ tf32 GEMM core (shared by both epilogues) ============
#define GEMM_TILE_B 16384
#define GEMM_SMEM  (6 * GEMM_TILE_B)

__device__ __forceinline__ void load_tile(const float* __restrict__ G, int row0,
                                          int k0, uint32_t s_tile, int tid) {
    #pragma unroll
    for (int i = 0; i < 4; i++) {
        int v = tid + i * 256;
        int r = v >> 3, c4 = v & 7;
        uint32_t dst = s_tile + (uint32_t)(r * 128 + ((c4 ^ (r & 7)) << 4));
        cp_async16(dst, G + (size_t)(row0 + r) * 256 + k0 + c4 * 4);
    }
}

// computes acc[4][4][4] for a 128x128 tile; caller does the epilogue
#define GEMM_MAINLOOP(X, W, m0, n0)                                           \
    load_tile(X, m0, 0, sbase, tid);                                          \
    load_tile(W, n0, 0, sbase + GEMM_TILE_B, tid);                            \
    CP_COMMIT();                                                              \
    load_tile(X, m0, 32, sbase + 2 * GEMM_TILE_B, tid);                       \
    load_tile(W, n0, 32, sbase + 3 * GEMM_TILE_B, tid);                       \
    CP_COMMIT();                                                              \
    _Pragma("unroll 1")                                                       \
    for (int c = 0; c < 8; c++) {                                             \
        if (c < 7) { CP_WAIT(1); } else { CP_WAIT(0); }                       \
        __syncthreads();                                                      \
        if (c + 2 < 8) {                                                      \
            uint32_t st = sbase + (uint32_t)(((c + 2) % 3) * 2 * GEMM_TILE_B);\
            load_tile(X, m0, (c + 2) * 32, st, tid);                          \
            load_tile(W, n0, (c + 2) * 32, st + GEMM_TILE_B, tid);            \
            CP_COMMIT();                                                      \
        }                                                                     \
        uint32_t sA = sbase + (uint32_t)((c % 3) * 2 * GEMM_TILE_B);          \
        uint32_t sB = sA + GEMM_TILE_B;                                       \
        _Pragma("unroll")                                                     \
        for (int ks = 0; ks < 4; ks++) {                                      \
            uint32_t a[4][4], b[2][4];                                        \
            _Pragma("unroll")                                                 \
            for (int mf = 0; mf < 4; mf++) {                                  \
                int m = a_row + mf * 16;                                      \
                uint32_t addr = sA + (uint32_t)(m * 128                       \
                              + (((2 * ks + a_hi) ^ (m & 7)) << 4));          \
                ldsm4(a[mf][0], a[mf][1], a[mf][2], a[mf][3], addr);          \
            }                                                                 \
            _Pragma("unroll")                                                 \
            for (int p = 0; p < 2; p++) {                                     \
                int n = b_row + p * 16;                                       \
                uint32_t addr = sB + (uint32_t)(n * 128                       \
                              + (((2 * ks + b_hi) ^ (n & 7)) << 4));          \
                ldsm4(b[p][0], b[p][1], b[p][2], b[p][3], addr);              \
            }                                                                 \
            _Pragma("unroll")                                                 \
            for (int mf = 0; mf < 4; mf++)                                    \
                _Pragma("unroll")                                             \
                for (int nf = 0; nf < 4; nf++)                                \
                    mma_tf32(acc[mf][nf][0], acc[mf][nf][1],                  \
                             acc[mf][nf][2], acc[mf][nf][3],                  \
                             a[mf][0], a[mf][1], a[mf][2], a[mf][3],          \
                             b[nf >> 1][(nf & 1) * 2],                        \
                             b[nf >> 1][(nf & 1) * 2 + 1]);                   \
        }                                                                     \
    }

// ---- QKV GEMM: special epilogue writes g_q / g_khi+g_klo / g_v ----
__global__ __launch_bounds__(256) void gemm_qkv(
    const float* __restrict__ X, const float* __restrict__ W,
    const float* __restrict__ bias)
{
    extern __shared__ char dsm[];
    uint32_t sbase = smem_to_u32(dsm);
    int tid = threadIdx.x;
    int wid = tid >> 5, lane = tid & 31;
    int warp_m = wid & 1, warp_n = wid >> 1;
    int m0 = blockIdx.y * 128;
    int n0 = blockIdx.x * 128;

    int a_row = warp_m * 64 + (lane & 7) + ((lane >> 3) & 1) * 8;
    int a_hi = lane >> 4;
    int b_row = warp_n * 32 + ((lane >> 4) & 1) * 8 + (lane & 7);
    int b_hi = (lane >> 3) & 1;

    float acc[4][4][4];
    #pragma unroll
    for (int i = 0; i < 4; i++)
        #pragma unroll
        for (int j = 0; j < 4; j++)
            #pragma unroll
            for (int t = 0; t < 4; t++) acc[i][j][t] = 0.0f;

    GEMM_MAINLOOP(X, W, m0, n0)

    int er = lane >> 2, ec = (lane & 3) * 2;
    int sel = n0 >> 8;                           // 0=Q 1=K 2=V
    #pragma unroll
    for (int mf = 0; mf < 4; mf++) {
        int row = m0 + warp_m * 64 + mf * 16 + er;
        #pragma unroll
        for (int nf = 0; nf < 4; nf++) {
            int col = n0 + warp_n * 32 + nf * 8 + ec;
            int cq = col & 255;
            float2 bv = *(const float2*)&bias[col];
            float v00 = acc[mf][nf][0] + bv.x;
            float v01 = acc[mf][nf][1] + bv.y;
            float v10 = acc[mf][nf][2] + bv.x;
            float v11 = acc[mf][nf][3] + bv.y;
            size_t o0 = (size_t)row * 256 + cq;
            size_t o1 = (size_t)(row + 8) * 256 + cq;
            if (sel == 0) {
                *(float2*)&g_q[o0] = make_float2(v00, v01);
                *(float2*)&g_q[o1] = make_float2(v10, v11);
            } else if (sel == 1) {
                float h00 = to_tf32f(v00), h01 = to_tf32f(v01);
                float h10 = to_tf32f(v10), h11 = to_tf32f(v11);
                *(float2*)&g_khi[o0] = make_float2(h00, h01);
                *(float2*)&g_khi[o1] = make_float2(h10, h11);
                *(float2*)&g_klo[o0] = make_float2(to_tf32f(v00 - h00),
                                                   to_tf32f(v01 - h01));
                *(float2*)&g_klo[o1] = make_float2(to_tf32f(v10 - h10),
                                                   to_tf32f(v11 - h11));
            } else {
                *(float2*)&g_v[o0] = make_float2(to_tf32f(v00), to_tf32f(v01));
                *(float2*)&g_v[o1] = make_float2(to_tf32f(v10), to_tf32f(v11));
            }
        }
    }
}

// ---- generic GEMM (output projection) ----
__global__ __launch_bounds__(256) void gemm_cp(
    const float* __restrict__ X, const float* __restrict__ W,
    const float* __restrict__ bias, float* __restrict__ Y, int Nn)
{
    extern __shared__ char dsm[];
    uint32_t sbase = smem_to_u32(dsm);
    int tid = threadIdx.x;
    int wid = tid >> 5, lane = tid & 31;
    int warp_m = wid & 1, warp_n = wid >> 1;
    int m0 = blockIdx.y * 128;
    int n0 = blockIdx.x * 128;

    int a_row = warp_m * 64 + (lane & 7) + ((lane >> 3) & 1) * 8;
    int a_hi = lane >> 4;
    int b_row = warp_n * 32 + ((lane >> 4) & 1) * 8 + (lane & 7);
    int b_hi = (lane >> 3) & 1;

    float acc[4][4][4];
    #pragma unroll
    for (int i = 0; i < 4; i++)
        #pragma unroll
        for (int j = 0; j < 4; j++)
            #pragma unroll
            for (int t = 0; t < 4; t++) acc[i][j][t] = 0.0f;

    GEMM_MAINLOOP(X, W, m0, n0)

    int er = lane >> 2, ec = (lane & 3) * 2;
    #pragma unroll
    for (int mf = 0; mf < 4; mf++) {
        int row = m0 + warp_m * 64 + mf * 16 + er;
        #pragma unroll
        for (int nf = 0; nf < 4; nf++) {
            int col = n0 + warp_n * 32 + nf * 8 + ec;
            float2 bv = *(const float2*)&bias[col];
            float2 o0, o1;
            o0.x = acc[mf][nf][0] + bv.x;
            o0.y = acc[mf][nf][1] + bv.y;
            o1.x = acc[mf][nf][2] + bv.x;
            o1.y = acc[mf][nf][3] + bv.y;
            *(float2*)&Y[(size_t)row * Nn + col] = o0;
            *(float2*)&Y[(size_t)(row + 8) * Nn + col] = o1;
        }
    }
}

// ------- gate kernel: compacted active-pair MLP (R13) -------
__global__ __launch_bounds__(256) void gate_kernel(
    const float* __restrict__ mask_g, const float* __restrict__ ef,
    const float* __restrict__ w1, const float* __restrict__ b1,
    const float* __restrict__ w2, const float* __restrict__ b2)
{
    __shared__ float sm[64 * 64];
    __shared__ float sw1[64], sb1[16], sw2[128], sb2[8];
    __shared__ uint16_t lst[4096];
    __shared__ int cnt;
    int blk = blockIdx.x;
    int tid = threadIdx.x;
    int lane = tid & 31;

    const float* mbase = mask_g + (size_t)blk * 4096;
    #pragma unroll
    for (int i = 0; i < 16; i++) sm[tid + i * 256] = mbase[tid + i * 256];
    if (tid < 64)  sw1[tid] = w1[tid];
    if (tid < 16)  sb1[tid] = b1[tid];
    if (tid < 128) sw2[tid] = w2[tid];
    if (tid < 8)   sb2[tid] = b2[tid];
    if (tid == 0)  cnt = 0;
    __syncthreads();

    if (tid < 64) {
        float s = 0.0f;
        for (int k = 0; k < 64; k++) s += sm[tid * 64 + k];
        if (s < 1.0f) sm[tid * 64 + tid] = 1.0f;
    }
    __syncthreads();

    #pragma unroll 1
    for (int it = 0; it < 16; it++) {
        int idx = tid + it * 256;
        int q = idx >> 6, k = idx & 63;
        bool act = (sm[idx] != 0.0f);
        float bias = -1e30f;
        if (act) bias = (q == k) ? 1.0f : ef[((size_t)blk * 4096 + idx) * 4 + 3];
        g_bias[(size_t)blk * 4096 + idx] = bias;
        if (!act) {
            __half* gp = g_gateh + (size_t)blk * 32768 + idx;
            __half z = __float2half_rn(0.0f);
            #pragma unroll
            for (int h = 0; h < 8; h++) gp[h * 4096] = z;
        }
        unsigned bal = __ballot_sync(0xffffffffu, act);
        int base = 0;
        if (lane == 0 && bal) base = atomicAdd(&cnt, __popc(bal));
        base = __shfl_sync(0xffffffffu, base, 0);
        if (act) {
            int pos = base + __popc(bal & ((1u << lane) - 1u));
            lst[pos] = (uint16_t)idx;
        }
    }
    __syncthreads();

    int n = cnt;
    #pragma unroll 1
    for (int i = tid; i < n; i += 256) {
        int idx = lst[i];
        int q = idx >> 6, k = idx & 63;
        float e0, e1, e2, e3;
        if (q == k) { e0 = e1 = e2 = 0.0f; e3 = 1.0f; }
        else {
            float4 ev = *(const float4*)(ef + ((size_t)blk * 4096 + idx) * 4);
            e0 = ev.x; e1 = ev.y; e2 = ev.z; e3 = ev.w;
        }
        float hh[16];
        #pragma unroll
        for (int j = 0; j < 16; j++) {
            float t = sb1[j] + sw1[j * 4] * e0 + sw1[j * 4 + 1] * e1
                    + sw1[j * 4 + 2] * e2 + sw1[j * 4 + 3] * e3;
            hh[j] = 0.5f * t * (1.0f + erf_fast(t * 0.70710678118654752f));
        }
        __half* gp = g_gateh + (size_t)blk * 32768 + idx;
        #pragma unroll
        for (int h = 0; h < 8; h++) {
            float s = sb2[h];
            #pragma unroll
            for (int j = 0; j < 16; j++) s += sw2[h * 16 + j] * hh[j];
            gp[h * 4096] = __float2half_rn(s);
        }
    }
}

// ------- attention: pipelined cp.async staging, reg softmax, 2 CTAs/SM -------
#define SC_OFF    0                 // [2][64][68]  P (probs+gate)
#define QH_OFF    8704              // [2][64][36]  Q raw fp32
#define KHI_OFF   13312             // [2][64][36]  K tf32-hi
#define KLO_OFF   17920             // [2][64][36]  K tf32-lo
#define VTHI_OFF  22528             // [2][32][68]  V^T tf32
#define ATTN_FLOATS 26880
#define ATTN_SMEM (ATTN_FLOATS * 4) // 105 KB -> 2 CTAs/SM

__global__ __launch_bounds__(256, 2) void attn_mma(
    const float* __restrict__ bias_g)
{
    extern __shared__ float smf[];
    uint32_t sbase = smem_to_u32(smf);

    int blk = blockIdx.x;
    int tid = threadIdx.x;
    int wid = tid >> 5, lane = tid & 31;
    int half = wid >> 2;
    int wg = wid & 3;
    int t0 = blk * 64;

    const float scale = 0.17677669529663687f;

    int a7 = (lane & 7) + ((lane >> 3) & 1) * 8;
    int ahi16 = (lane >> 4) * 16;
    int b7 = (lane & 7) + ((lane >> 4) & 1) * 8;
    int bhi16 = ((lane >> 3) & 1) * 16;
    int er = lane >> 2, ec = (lane & 3) * 2;

    auto stageQK = [&](int it2) {
        #pragma unroll
        for (int j = 0; j < 4; j++) {
            int c = tid + j * 256;
            int sh = c >> 9;
            int rem = c & 511;
            int t = rem >> 3, c4 = rem & 7;
            int head = it2 * 2 + sh;
            size_t gofs = (size_t)(t0 + t) * 256 + head * 32 + c4 * 4;
            uint32_t sofs = (uint32_t)((sh * 2304 + t * 36 + c4 * 4) * 4);
            cp_async16(sbase + QH_OFF * 4 + sofs, g_q + gofs);
            cp_async16(sbase + KHI_OFF * 4 + sofs, g_khi + gofs);
            cp_async16(sbase + KLO_OFF * 4 + sofs, g_klo + gofs);
        }
    };
    auto stageV = [&](int it2) {
        #pragma unroll
        for (int j = 0; j < 4; j++) {
            int c = tid + j * 256;
            int sh = c >> 9;
            int rem = c & 511;
            int t = rem >> 3, c4 = rem & 7;
            int head = it2 * 2 + sh;
            float4 vv = *(const float4*)(g_v + (size_t)(t0 + t) * 256
                                         + head * 32 + c4 * 4);
            float* vh = &smf[VTHI_OFF + sh * 2176 + (c4 * 4) * 68 + t];
            vh[0] = vv.x; vh[68] = vv.y; vh[136] = vv.z; vh[204] = vv.w;
        }
    };

    // prologue: stage it=0
    stageQK(0); CP_COMMIT();
    stageV(0);
    CP_WAIT(0);
    __syncthreads();

    #pragma unroll 1
    for (int it = 0; it < 4; it++) {
        int head = it * 2 + half;

        // ---- QK^T (3xTF32), rows [wg*16,+16) x all 64 cols ----
        float acc[8][4];
        #pragma unroll
        for (int nt = 0; nt < 8; nt++)
            #pragma unroll
            for (int t = 0; t < 4; t++) acc[nt][t] = 0.0f;
        {
            uint32_t sQ  = sbase + (QH_OFF + half * 2304) * 4;
            uint32_t sKh = sbase + (KHI_OFF + half * 2304) * 4;
            uint32_t sKl = sbase + (KLO_OFF + half * 2304) * 4;
            uint32_t aAddr  = sQ + (uint32_t)((wg * 16 + a7) * 144 + ahi16);
            uint32_t bAddrH = sKh + (uint32_t)(b7 * 144 + bhi16);
            uint32_t bAddrL = sKl + (uint32_t)(b7 * 144 + bhi16);

            #pragma unroll
            for (int ks = 0; ks < 4; ks++) {
                uint32_t a[4], ah[4], al[4];
                ldsm4(a[0], a[1], a[2], a[3], aAddr + ks * 32);
                #pragma unroll
                for (int t = 0; t < 4; t++) split_tf32(a[t], ah[t], al[t]);
                uint32_t bh[4][4], bl[4][4];
                #pragma unroll
                for (int p = 0; p < 4; p++) {
                    ldsm4(bh[p][0], bh[p][1], bh[p][2], bh[p][3],
                          bAddrH + (uint32_t)(p * 16 * 144) + ks * 32);
                    ldsm4(bl[p][0], bl[p][1], bl[p][2], bl[p][3],
                          bAddrL + (uint32_t)(p * 16 * 144) + ks * 32);
                }
                #pragma unroll
                for (int nt = 0; nt < 8; nt++) {
                    int p = nt >> 1, i0 = (nt & 1) * 2;
                    mma_tf32(acc[nt][0], acc[nt][1], acc[nt][2], acc[nt][3],
                             ah[0], ah[1], ah[2], ah[3], bh[p][i0], bh[p][i0 + 1]);
                    mma_tf32(acc[nt][0], acc[nt][1], acc[nt][2], acc[nt][3],
                             ah[0], ah[1], ah[2], ah[3], bl[p][i0], bl[p][i0 + 1]);
                    mma_tf32(acc[nt][0], acc[nt][1], acc[nt][2], acc[nt][3],
                             al[0], al[1], al[2], al[3], bh[p][i0], bh[p][i0 + 1]);
                }
            }
        }
        __syncthreads();                         // Q/K tiles now dead

        // ---- prefetch next iteration's Q/K under softmax+PV ----
        if (it < 3) { stageQK(it + 1); CP_COMMIT(); }

        // ---- bias + softmax + gate, entirely in registers ----
        int r0 = wg * 16 + er;
        {
            const float* bb = bias_g + (size_t)blk * 4096;
            float m0 = -3.0e38f, m1 = -3.0e38f;
            #pragma unroll
            for (int nt = 0; nt < 8; nt++) {
                int col = nt * 8 + ec;
                float2 b0 = *(const float2*)&bb[r0 * 64 + col];
                float2 b1 = *(const float2*)&bb[(r0 + 8) * 64 + col];
                acc[nt][0] = acc[nt][0] * scale + b0.x;
                acc[nt][1] = acc[nt][1] * scale + b0.y;
                acc[nt][2] = acc[nt][2] * scale + b1.x;
                acc[nt][3] = acc[nt][3] * scale + b1.y;
                m0 = fmaxf(m0, fmaxf(acc[nt][0], acc[nt][1]));
                m1 = fmaxf(m1, fmaxf(acc[nt][2], acc[nt][3]));
            }
            m0 = fmaxf(m0, __shfl_xor_sync(0xffffffffu, m0, 1));
            m0 = fmaxf(m0, __shfl_xor_sync(0xffffffffu, m0, 2));
            m1 = fmaxf(m1, __shfl_xor_sync(0xffffffffu, m1, 1));
            m1 = fmaxf(m1, __shfl_xor_sync(0xffffffffu, m1, 2));
            float s0 = 0.0f, s1 = 0.0f;
            #pragma unroll
            for (int nt = 0; nt < 8; nt++) {
                acc[nt][0] = __expf(acc[nt][0] - m0); s0 += acc[nt][0];
                acc[nt][1] = __expf(acc[nt][1] - m0); s0 += acc[nt][1];
                acc[nt][2] = __expf(acc[nt][2] - m1); s1 += acc[nt][2];
                acc[nt][3] = __expf(acc[nt][3] - m1); s1 += acc[nt][3];
            }
            s0 += __shfl_xor_sync(0xffffffffu, s0, 1);
            s0 += __shfl_xor_sync(0xffffffffu, s0, 2);
            s1 += __shfl_xor_sync(0xffffffffu, s1, 1);
            s1 += __shfl_xor_sync(0xffffffffu, s1, 2);
            float inv0 = 1.0f / s0, inv1 = 1.0f / s1;

            const __half* gb = g_gateh + (size_t)blk * 32768 + (size_t)head * 4096;
            float* Scm = &smf[SC_OFF + half * 4352];
            #pragma unroll
            for (int nt = 0; nt < 8; nt++) {
                int col = nt * 8 + ec;
                float2 g0 = __half22float2(*(const __half2*)(gb + r0 * 64 + col));
                float2 g1 = __half22float2(*(const __half2*)(gb + (r0 + 8) * 64 + col));
                float2 p0, p1;
                p0.x = acc[nt][0] * inv0 + g0.x;
                p0.y = acc[nt][1] * inv0 + g0.y;
                p1.x = acc[nt][2] * inv1 + g1.x;
                p1.y = acc[nt][3] * inv1 + g1.y;
                *(float2*)&Scm[r0 * 68 + col] = p0;
                *(float2*)&Scm[(r0 + 8) * 68 + col] = p1;
            }
        }
        __syncwarp();                            // own rows: warp-local visibility

        // ---- PV (2-term: P split, V plain tf32): rows [wg*16,+16) x 32 dims ----
        {
            uint32_t sP  = sbase + (SC_OFF + half * 4352) * 4;
            uint32_t sVh = sbase + (VTHI_OFF + half * 2176) * 4;
            uint32_t aAddr  = sP + (uint32_t)((wg * 16 + a7) * 272 + ahi16);
            uint32_t bAddrH = sVh + (uint32_t)(b7 * 272 + bhi16);

            float pacc[4][4];
            #pragma unroll
            for (int nt = 0; nt < 4; nt++)
                #pragma unroll
                for (int t = 0; t < 4; t++) pacc[nt][t] = 0.0f;

            #pragma unroll
            for (int ks = 0; ks < 8; ks++) {
                uint32_t a[4], ah[4], al[4];
                ldsm4(a[0], a[1], a[2], a[3], aAddr + ks * 32);
                #pragma unroll
                for (int t = 0; t < 4; t++) split_tf32(a[t], ah[t], al[t]);
                uint32_t bh[2][4];
                #pragma unroll
                for (int p = 0; p < 2; p++)
                    ldsm4(bh[p][0], bh[p][1], bh[p][2], bh[p][3],
                          bAddrH + (uint32_t)(p * 16 * 272) + ks * 32);
                #pragma unroll
                for (int nt = 0; nt < 4; nt++) {
                    int p = nt >> 1, i0 = (nt & 1) * 2;
                    mma_tf32(pacc[nt][0], pacc[nt][1], pacc[nt][2], pacc[nt][3],
                             ah[0], ah[1], ah[2], ah[3], bh[p][i0], bh[p][i0 + 1]);
                    mma_tf32(pacc[nt][0], pacc[nt][1], pacc[nt][2], pacc[nt][3],
                             al[0], al[1], al[2], al[3], bh[p][i0], bh[p][i0 + 1]);
                }
            }

            float* og0 = g_xm + (size_t)(t0 + r0) * 256 + head * 32;
            float* og1 = g_xm + (size_t)(t0 + r0 + 8) * 256 + head * 32;
            #pragma unroll
            for (int nt = 0; nt < 4; nt++) {
                int col = nt * 8 + ec;
                *(float2*)&og0[col] = make_float2(to_tf32f(pacc[nt][0]),
                                                  to_tf32f(pacc[nt][1]));
                *(float2*)&og1[col] = make_float2(to_tf32f(pacc[nt][2]),
                                                  to_tf32f(pacc[nt][3]));
            }
        }

        // ---- epilogue of iter: land prefetch + restage V ----
        if (it < 3) {
            CP_WAIT(0);
            __syncthreads();                     // Q/K arrived; VT reads done
            stageV(it + 1);
            __syncthreads();                     // VT ready
        }
    }
}

// ---------------- launch ----------------
extern "C" void kernel_launch(void* const* d_in, const int* in_sizes, int n_in,
                              void* d_out, int out_size)
{
    const float* x      = (const float*)d_in[0];
    const float* amask  = (const float*)d_in[1];
    const float* efeat  = (const float*)d_in[2];
    const float* qkv_w  = (const float*)d_in[3];
    const float* qkv_b  = (const float*)d_in[4];
    const float* proj_w = (const float*)d_in[5];
    const float* proj_b = (const float*)d_in[6];
    const float* eg_w1  = (const float*)d_in[7];
    const float* eg_b1  = (const float*)d_in[8];
    const float* eg_w2  = (const float*)d_in[9];
    const float* eg_b2  = (const float*)d_in[10];
    float* out = (float*)d_out;

    void* p_xc = nullptr; void* p_wc = nullptr;
    void* p_xm = nullptr; void* p_bias = nullptr;
    cudaGetSymbolAddress(&p_xc, g_xc);
    cudaGetSymbolAddress(&p_wc, g_wc);
    cudaGetSymbolAddress(&p_xm, g_xm);
    cudaGetSymbolAddress(&p_bias, g_bias);
    float* xc = (float*)p_xc;
    float* wc = (float*)p_wc;

    cudaFuncSetAttribute(attn_mma,
                         cudaFuncAttributeMaxDynamicSharedMemorySize, ATTN_SMEM);
    cudaFuncSetAttribute(gemm_cp,
                         cudaFuncAttributeMaxDynamicSharedMemorySize, GEMM_SMEM);
    cudaFuncSetAttribute(gemm_qkv,
                         cudaFuncAttributeMaxDynamicSharedMemorySize, GEMM_SMEM);

    // 0) merged tf32 pre-round (x | qkv_w | proj_w)
    cvt_all_k<<<(N4ALL + 255) / 256, 256>>>(
        (const float4*)x, (const float4*)qkv_w, (const float4*)proj_w,
        (float4*)xc, (float4*)wc);

    // 1) QKV projection -> g_q / g_khi,g_klo / g_v
    gemm_qkv<<<dim3(768 / 128, NTOK / 128), 256, GEMM_SMEM>>>(xc, wc, qkv_b);

    // 2) edge gate + bias matrix (compacted)
    gate_kernel<<<NBLK, 256>>>(amask, efeat, eg_w1, eg_b1, eg_w2, eg_b2);

    // 3) block attention (pipelined staging; profiled slot)
    attn_mma<<<NBLK, 256, ATTN_SMEM>>>((const float*)p_bias);

    // 4) output projection
    gemm_cp<<<dim3(CC / 128, NTOK / 128), 256, GEMM_SMEM>>>(
        (const float*)p_xm, wc + 768 * CC, proj_b, out, CC);
}

// round 17
// speedup vs baseline: 1.0537x; 1.0537x over previous
#include <cuda_runtime.h>
#include <cuda_fp16.h>
#include <math.h>
#include <cstdint>

// Problem constants
#define BB    4
#define NTOK  32768          // B*N
#define CC    256
#define HH    8
#define HD    32
#define LL    64
#define NBLK  512            // B * NB
#define EGH   16

// ---------------- scratch (device globals; no allocs allowed) ----------------
__device__ float  g_q  [(size_t)NTOK * CC];            // Q raw fp32
__device__ float  g_k  [(size_t)NTOK * CC];            // K tf32
__device__ float  g_v  [(size_t)NTOK * CC];            // V tf32
__device__ float  g_xc[(size_t)NTOK * CC];             // x pre-rounded to tf32
__device__ float  g_wc[(size_t)(768 + 256) * CC];      // qkv_w | proj_w, tf32-rounded
__device__ __half g_gateh[(size_t)NBLK * 8 * 64 * 64]; // [blk][h][q][k] fp16
__device__ float  g_bias[(size_t)NBLK * 64 * 64];      // [blk][q][k] bias or -1e30
__device__ float  g_xm[(size_t)NTOK * CC];             // attn out (tf32-rounded)

// ======================= PTX helpers =======================
__device__ __forceinline__ uint32_t smem_to_u32(const void* p) {
    uint32_t a;
    asm("{ .reg .u64 t; cvta.to.shared.u64 t, %1; cvt.u32.u64 %0, t; }"
        : "=r"(a) : "l"(p));
    return a;
}

__device__ __forceinline__ void cp_async16(uint32_t smem_addr, const void* gptr) {
    asm volatile("cp.async.cg.shared.global [%0], [%1], 16;"
                 :: "r"(smem_addr), "l"(gptr));
}
#define CP_COMMIT() asm volatile("cp.async.commit_group;" ::: "memory")
#define CP_WAIT(n)  asm volatile("cp.async.wait_group %0;" :: "n"(n) : "memory")

__device__ __forceinline__ void ldsm4(uint32_t& r0, uint32_t& r1, uint32_t& r2,
                                      uint32_t& r3, uint32_t addr) {
    asm volatile("ldmatrix.sync.aligned.m8n8.x4.shared.b16 {%0,%1,%2,%3}, [%4];"
                 : "=r"(r0), "=r"(r1), "=r"(r2), "=r"(r3) : "r"(addr));
}

__device__ __forceinline__ uint32_t to_tf32(uint32_t x) {
    uint32_t y;
    asm("cvt.rna.tf32.f32 %0, %1;" : "=r"(y) : "r"(x));
    return y;
}

__device__ __forceinline__ float to_tf32f(float x) {
    return __uint_as_float(to_tf32(__float_as_uint(x)));
}

__device__ __forceinline__ void split_tf32(uint32_t x, uint32_t& hi, uint32_t& lo) {
    hi = to_tf32(x);
    float r = __uint_as_float(x) - __uint_as_float(hi);
    lo = to_tf32(__float_as_uint(r));
}

__device__ __forceinline__ void mma_tf32(float& c0, float& c1, float& c2, float& c3,
                                         uint32_t a0, uint32_t a1, uint32_t a2, uint32_t a3,
                                         uint32_t b0, uint32_t b1) {
    asm volatile(
        "mma.sync.aligned.m16n8k8.row.col.f32.tf32.tf32.f32 "
        "{%0,%1,%2,%3}, {%4,%5,%6,%7}, {%8,%9}, {%0,%1,%2,%3};"
        : "+f"(c0), "+f"(c1), "+f"(c2), "+f"(c3)
        : "r"(a0), "r"(a1), "r"(a2), "r"(a3), "r"(b0), "r"(b1));
}

// fast erf: Abramowitz-Stegun 7.1.26, |abs err| <= 1.5e-7
__device__ __forceinline__ float erf_fast(float x) {
    float ax = fabsf(x);
    float t = __frcp_rn(fmaf(0.3275911f, ax, 1.0f));
    float y = t * fmaf(t, fmaf(t, fmaf(t, fmaf(t, 1.061405429f, -1.453152027f),
                                       1.421413741f), -0.284496736f), 0.254829592f);
    float r = 1.0f - y * __expf(-ax * ax);
    return copysignf(r, x);
}

// ---------------- merged tf32 pre-round pass (x | qkv_w | proj_w) ----------------
#define N4X  (NTOK * CC / 4)
#define N4W1 (768 * CC / 4)
#define N4W2 (CC * CC / 4)
#define N4ALL (N4X + N4W1 + N4W2)

__global__ __launch_bounds__(256) void cvt_all_k(
    const float4* __restrict__ x, const float4* __restrict__ w1,
    const float4* __restrict__ w2, float4* __restrict__ xc,
    float4* __restrict__ wc)
{
    int i = blockIdx.x * blockDim.x + threadIdx.x;
    if (i >= N4ALL) return;
    const float4* s;
    float4* d;
    if (i < N4X)              { s = x + i;               d = xc + i; }
    else if (i < N4X + N4W1)  { int j = i - N4X;         s = w1 + j; d = wc + j; }
    else                      { int j = i - N4X - N4W1;  s = w2 + j; d = wc + N4W1 + j; }
    float4 v = *s;
    v.x = to_tf32f(v.x); v.y = to_tf32f(v.y);
    v.z = to_tf32f(v.z); v.w = to_tf32f(v.w);
    *d = v;
}

// ============ tf32 GEMM core (shared by both epilogues) ============
#define GEMM_TILE_B 16384
#define GEMM_SMEM  (6 * GEMM_TILE_B)

__device__ __forceinline__ void load_tile(const float* __restrict__ G, int row0,
                                          int k0, uint32_t s_tile, int tid) {
    #pragma unroll
    for (int i = 0; i < 4; i++) {
        int v = tid + i * 256;
        int r = v >> 3, c4 = v & 7;
        uint32_t dst = s_tile + (uint32_t)(r * 128 + ((c4 ^ (r & 7)) << 4));
        cp_async16(dst, G + (size_t)(row0 + r) * 256 + k0 + c4 * 4);
    }
}

// computes acc[4][4][4] for a 128x128 tile; caller does the epilogue
#define GEMM_MAINLOOP(X, W, m0, n0)                                           \
    load_tile(X, m0, 0, sbase, tid);                                          \
    load_tile(W, n0, 0, sbase + GEMM_TILE_B, tid);                            \
    CP_COMMIT();                                                              \
    load_tile(X, m0, 32, sbase + 2 * GEMM_TILE_B, tid);                       \
    load_tile(W, n0, 32, sbase + 3 * GEMM_TILE_B, tid);                       \
    CP_COMMIT();                                                              \
    _Pragma("unroll 1")                                                       \
    for (int c = 0; c < 8; c++) {                                             \
        if (c < 7) { CP_WAIT(1); } else { CP_WAIT(0); }                       \
        __syncthreads();                                                      \
        if (c + 2 < 8) {                                                      \
            uint32_t st = sbase + (uint32_t)(((c + 2) % 3) * 2 * GEMM_TILE_B);\
            load_tile(X, m0, (c + 2) * 32, st, tid);                          \
            load_tile(W, n0, (c + 2) * 32, st + GEMM_TILE_B, tid);            \
            CP_COMMIT();                                                      \
        }                                                                     \
        uint32_t sA = sbase + (uint32_t)((c % 3) * 2 * GEMM_TILE_B);          \
        uint32_t sB = sA + GEMM_TILE_B;                                       \
        _Pragma("unroll")                                                     \
        for (int ks = 0; ks < 4; ks++) {                                      \
            uint32_t a[4][4], b[2][4];                                        \
            _Pragma("unroll")                                                 \
            for (int mf = 0; mf < 4; mf++) {                                  \
                int m = a_row + mf * 16;                                      \
                uint32_t addr = sA + (uint32_t)(m * 128                       \
                              + (((2 * ks + a_hi) ^ (m & 7)) << 4));          \
                ldsm4(a[mf][0], a[mf][1], a[mf][2], a[mf][3], addr);          \
            }                                                                 \
            _Pragma("unroll")                                                 \
            for (int p = 0; p < 2; p++) {                                     \
                int n = b_row + p * 16;                                       \
                uint32_t addr = sB + (uint32_t)(n * 128                       \
                              + (((2 * ks + b_hi) ^ (n & 7)) << 4));          \
                ldsm4(b[p][0], b[p][1], b[p][2], b[p][3], addr);              \
            }                                                                 \
            _Pragma("unroll")                                                 \
            for (int mf = 0; mf < 4; mf++)                                    \
                _Pragma("unroll")                                             \
                for (int nf = 0; nf < 4; nf++)                                \
                    mma_tf32(acc[mf][nf][0], acc[mf][nf][1],                  \
                             acc[mf][nf][2], acc[mf][nf][3],                  \
                             a[mf][0], a[mf][1], a[mf][2], a[mf][3],          \
                             b[nf >> 1][(nf & 1) * 2],                        \
                             b[nf >> 1][(nf & 1) * 2 + 1]);                   \
        }                                                                     \
    }

// ---- QKV GEMM: epilogue writes g_q (raw) / g_k, g_v (tf32-rounded) ----
__global__ __launch_bounds__(256) void gemm_qkv(
    const float* __restrict__ X, const float* __restrict__ W,
    const float* __restrict__ bias)
{
    extern __shared__ char dsm[];
    uint32_t sbase = smem_to_u32(dsm);
    int tid = threadIdx.x;
    int wid = tid >> 5, lane = tid & 31;
    int warp_m = wid & 1, warp_n = wid >> 1;
    int m0 = blockIdx.y * 128;
    int n0 = blockIdx.x * 128;

    int a_row = warp_m * 64 + (lane & 7) + ((lane >> 3) & 1) * 8;
    int a_hi = lane >> 4;
    int b_row = warp_n * 32 + ((lane >> 4) & 1) * 8 + (lane & 7);
    int b_hi = (lane >> 3) & 1;

    float acc[4][4][4];
    #pragma unroll
    for (int i = 0; i < 4; i++)
        #pragma unroll
        for (int j = 0; j < 4; j++)
            #pragma unroll
            for (int t = 0; t < 4; t++) acc[i][j][t] = 0.0f;

    GEMM_MAINLOOP(X, W, m0, n0)

    int er = lane >> 2, ec = (lane & 3) * 2;
    int sel = n0 >> 8;                           // 0=Q 1=K 2=V
    float* dst = (sel == 0) ? g_q : ((sel == 1) ? g_k : g_v);
    #pragma unroll
    for (int mf = 0; mf < 4; mf++) {
        int row = m0 + warp_m * 64 + mf * 16 + er;
        #pragma unroll
        for (int nf = 0; nf < 4; nf++) {
            int col = n0 + warp_n * 32 + nf * 8 + ec;
            int cq = col & 255;
            float2 bv = *(const float2*)&bias[col];
            float v00 = acc[mf][nf][0] + bv.x;
            float v01 = acc[mf][nf][1] + bv.y;
            float v10 = acc[mf][nf][2] + bv.x;
            float v11 = acc[mf][nf][3] + bv.y;
            if (sel != 0) {
                v00 = to_tf32f(v00); v01 = to_tf32f(v01);
                v10 = to_tf32f(v10); v11 = to_tf32f(v11);
            }
            *(float2*)&dst[(size_t)row * 256 + cq] = make_float2(v00, v01);
            *(float2*)&dst[(size_t)(row + 8) * 256 + cq] = make_float2(v10, v11);
        }
    }
}

// ---- generic GEMM (output projection) ----
__global__ __launch_bounds__(256) void gemm_cp(
    const float* __restrict__ X, const float* __restrict__ W,
    const float* __restrict__ bias, float* __restrict__ Y, int Nn)
{
    extern __shared__ char dsm[];
    uint32_t sbase = smem_to_u32(dsm);
    int tid = threadIdx.x;
    int wid = tid >> 5, lane = tid & 31;
    int warp_m = wid & 1, warp_n = wid >> 1;
    int m0 = blockIdx.y * 128;
    int n0 = blockIdx.x * 128;

    int a_row = warp_m * 64 + (lane & 7) + ((lane >> 3) & 1) * 8;
    int a_hi = lane >> 4;
    int b_row = warp_n * 32 + ((lane >> 4) & 1) * 8 + (lane & 7);
    int b_hi = (lane >> 3) & 1;

    float acc[4][4][4];
    #pragma unroll
    for (int i = 0; i < 4; i++)
        #pragma unroll
        for (int j = 0; j < 4; j++)
            #pragma unroll
            for (int t = 0; t < 4; t++) acc[i][j][t] = 0.0f;

    GEMM_MAINLOOP(X, W, m0, n0)

    int er = lane >> 2, ec = (lane & 3) * 2;
    #pragma unroll
    for (int mf = 0; mf < 4; mf++) {
        int row = m0 + warp_m * 64 + mf * 16 + er;
        #pragma unroll
        for (int nf = 0; nf < 4; nf++) {
            int col = n0 + warp_n * 32 + nf * 8 + ec;
            float2 bv = *(const float2*)&bias[col];
            float2 o0, o1;
            o0.x = acc[mf][nf][0] + bv.x;
            o0.y = acc[mf][nf][1] + bv.y;
            o1.x = acc[mf][nf][2] + bv.x;
            o1.y = acc[mf][nf][3] + bv.y;
            *(float2*)&Y[(size_t)row * Nn + col] = o0;
            *(float2*)&Y[(size_t)(row + 8) * Nn + col] = o1;
        }
    }
}

// ------- gate kernel: compacted active-pair MLP (R13) -------
__global__ __launch_bounds__(256) void gate_kernel(
    const float* __restrict__ mask_g, const float* __restrict__ ef,
    const float* __restrict__ w1, const float* __restrict__ b1,
    const float* __restrict__ w2, const float* __restrict__ b2)
{
    __shared__ float sm[64 * 64];
    __shared__ float sw1[64], sb1[16], sw2[128], sb2[8];
    __shared__ uint16_t lst[4096];
    __shared__ int cnt;
    int blk = blockIdx.x;
    int tid = threadIdx.x;
    int lane = tid & 31;

    const float* mbase = mask_g + (size_t)blk * 4096;
    #pragma unroll
    for (int i = 0; i < 16; i++) sm[tid + i * 256] = mbase[tid + i * 256];
    if (tid < 64)  sw1[tid] = w1[tid];
    if (tid < 16)  sb1[tid] = b1[tid];
    if (tid < 128) sw2[tid] = w2[tid];
    if (tid < 8)   sb2[tid] = b2[tid];
    if (tid == 0)  cnt = 0;
    __syncthreads();

    if (tid < 64) {
        float s = 0.0f;
        for (int k = 0; k < 64; k++) s += sm[tid * 64 + k];
        if (s < 1.0f) sm[tid * 64 + tid] = 1.0f;
    }
    __syncthreads();

    #pragma unroll 1
    for (int it = 0; it < 16; it++) {
        int idx = tid + it * 256;
        int q = idx >> 6, k = idx & 63;
        bool act = (sm[idx] != 0.0f);
        float bias = -1e30f;
        if (act) bias = (q == k) ? 1.0f : ef[((size_t)blk * 4096 + idx) * 4 + 3];
        g_bias[(size_t)blk * 4096 + idx] = bias;
        if (!act) {
            __half* gp = g_gateh + (size_t)blk * 32768 + idx;
            __half z = __float2half_rn(0.0f);
            #pragma unroll
            for (int h = 0; h < 8; h++) gp[h * 4096] = z;
        }
        unsigned bal = __ballot_sync(0xffffffffu, act);
        int base = 0;
        if (lane == 0 && bal) base = atomicAdd(&cnt, __popc(bal));
        base = __shfl_sync(0xffffffffu, base, 0);
        if (act) {
            int pos = base + __popc(bal & ((1u << lane) - 1u));
            lst[pos] = (uint16_t)idx;
        }
    }
    __syncthreads();

    int n = cnt;
    #pragma unroll 1
    for (int i = tid; i < n; i += 256) {
        int idx = lst[i];
        int q = idx >> 6, k = idx & 63;
        float e0, e1, e2, e3;
        if (q == k) { e0 = e1 = e2 = 0.0f; e3 = 1.0f; }
        else {
            float4 ev = *(const float4*)(ef + ((size_t)blk * 4096 + idx) * 4);
            e0 = ev.x; e1 = ev.y; e2 = ev.z; e3 = ev.w;
        }
        float hh[16];
        #pragma unroll
        for (int j = 0; j < 16; j++) {
            float t = sb1[j] + sw1[j * 4] * e0 + sw1[j * 4 + 1] * e1
                    + sw1[j * 4 + 2] * e2 + sw1[j * 4 + 3] * e3;
            hh[j] = 0.5f * t * (1.0f + erf_fast(t * 0.70710678118654752f));
        }
        __half* gp = g_gateh + (size_t)blk * 32768 + idx;
        #pragma unroll
        for (int h = 0; h < 8; h++) {
            float s = sb2[h];
            #pragma unroll
            for (int j = 0; j < 16; j++) s += sw2[h * 16 + j] * hh[j];
            gp[h * 4096] = __float2half_rn(s);
        }
    }
}

// ------- attention: cp.async staging, 2-term QK + 2-term PV, reg softmax -------
#define SC_OFF    0                 // [2][64][68]  P (probs+gate)
#define QH_OFF    8704              // [2][64][36]  Q raw fp32
#define KH_OFF    13312             // [2][64][36]  K tf32
#define VT_OFF    17920             // [2][32][68]  V^T tf32
#define ATTN_FLOATS 22272
#define ATTN_SMEM (ATTN_FLOATS * 4) // 89088 B -> 2 CTAs/SM

__global__ __launch_bounds__(256, 2) void attn_mma(
    const float* __restrict__ bias_g)
{
    extern __shared__ float smf[];
    uint32_t sbase = smem_to_u32(smf);

    int blk = blockIdx.x;
    int tid = threadIdx.x;
    int wid = tid >> 5, lane = tid & 31;
    int half = wid >> 2;
    int wg = wid & 3;
    int t0 = blk * 64;

    const float scale = 0.17677669529663687f;

    int a7 = (lane & 7) + ((lane >> 3) & 1) * 8;
    int ahi16 = (lane >> 4) * 16;
    int b7 = (lane & 7) + ((lane >> 4) & 1) * 8;
    int bhi16 = ((lane >> 3) & 1) * 16;
    int er = lane >> 2, ec = (lane & 3) * 2;

    #pragma unroll 1
    for (int it = 0; it < 4; it++) {
        if (it) __syncthreads();

        // ---- cp.async stage Q, K; LDG-transpose V ----
        #pragma unroll
        for (int j = 0; j < 4; j++) {
            int c = tid + j * 256;
            int sh = c >> 9;
            int rem = c & 511;
            int t = rem >> 3, c4 = rem & 7;
            int head = it * 2 + sh;
            size_t gofs = (size_t)(t0 + t) * 256 + head * 32 + c4 * 4;
            uint32_t sofs = (uint32_t)((sh * 2304 + t * 36 + c4 * 4) * 4);
            cp_async16(sbase + QH_OFF * 4 + sofs, g_q + gofs);
            cp_async16(sbase + KH_OFF * 4 + sofs, g_k + gofs);
        }
        CP_COMMIT();
        #pragma unroll
        for (int j = 0; j < 4; j++) {
            int c = tid + j * 256;
            int sh = c >> 9;
            int rem = c & 511;
            int t = rem >> 3, c4 = rem & 7;
            int head = it * 2 + sh;
            float4 vv = *(const float4*)(g_v + (size_t)(t0 + t) * 256
                                         + head * 32 + c4 * 4);
            float* vh = &smf[VT_OFF + sh * 2176 + (c4 * 4) * 68 + t];
            vh[0] = vv.x; vh[68] = vv.y; vh[136] = vv.z; vh[204] = vv.w;
        }
        CP_WAIT(0);
        __syncthreads();

        int head = it * 2 + half;

        // ---- QK^T (2-term: Q split, K plain tf32), rows [wg*16,+16) x 64 cols ----
        float acc[8][4];
        #pragma unroll
        for (int nt = 0; nt < 8; nt++)
            #pragma unroll
            for (int t = 0; t < 4; t++) acc[nt][t] = 0.0f;
        {
            uint32_t sQ = sbase + (QH_OFF + half * 2304) * 4;
            uint32_t sK = sbase + (KH_OFF + half * 2304) * 4;
            uint32_t aAddr = sQ + (uint32_t)((wg * 16 + a7) * 144 + ahi16);
            uint32_t bAddr = sK + (uint32_t)(b7 * 144 + bhi16);

            #pragma unroll
            for (int ks = 0; ks < 4; ks++) {
                uint32_t a[4], ah[4], al[4];
                ldsm4(a[0], a[1], a[2], a[3], aAddr + ks * 32);
                #pragma unroll
                for (int t = 0; t < 4; t++) split_tf32(a[t], ah[t], al[t]);
                uint32_t bh[4][4];
                #pragma unroll
                for (int p = 0; p < 4; p++)
                    ldsm4(bh[p][0], bh[p][1], bh[p][2], bh[p][3],
                          bAddr + (uint32_t)(p * 16 * 144) + ks * 32);
                #pragma unroll
                for (int nt = 0; nt < 8; nt++) {
                    int p = nt >> 1, i0 = (nt & 1) * 2;
                    mma_tf32(acc[nt][0], acc[nt][1], acc[nt][2], acc[nt][3],
                             ah[0], ah[1], ah[2], ah[3], bh[p][i0], bh[p][i0 + 1]);
                    mma_tf32(acc[nt][0], acc[nt][1], acc[nt][2], acc[nt][3],
                             al[0], al[1], al[2], al[3], bh[p][i0], bh[p][i0 + 1]);
                }
            }
        }

        // ---- bias + softmax + gate, entirely in registers ----
        int r0 = wg * 16 + er;
        {
            const float* bb = bias_g + (size_t)blk * 4096;
            float m0 = -3.0e38f, m1 = -3.0e38f;
            #pragma unroll
            for (int nt = 0; nt < 8; nt++) {
                int col = nt * 8 + ec;
                float2 b0 = *(const float2*)&bb[r0 * 64 + col];
                float2 b1 = *(const float2*)&bb[(r0 + 8) * 64 + col];
                acc[nt][0] = acc[nt][0] * scale + b0.x;
                acc[nt][1] = acc[nt][1] * scale + b0.y;
                acc[nt][2] = acc[nt][2] * scale + b1.x;
                acc[nt][3] = acc[nt][3] * scale + b1.y;
                m0 = fmaxf(m0, fmaxf(acc[nt][0], acc[nt][1]));
                m1 = fmaxf(m1, fmaxf(acc[nt][2], acc[nt][3]));
            }
            m0 = fmaxf(m0, __shfl_xor_sync(0xffffffffu, m0, 1));
            m0 = fmaxf(m0, __shfl_xor_sync(0xffffffffu, m0, 2));
            m1 = fmaxf(m1, __shfl_xor_sync(0xffffffffu, m1, 1));
            m1 = fmaxf(m1, __shfl_xor_sync(0xffffffffu, m1, 2));
            float s0 = 0.0f, s1 = 0.0f;
            #pragma unroll
            for (int nt = 0; nt < 8; nt++) {
                acc[nt][0] = __expf(acc[nt][0] - m0); s0 += acc[nt][0];
                acc[nt][1] = __expf(acc[nt][1] - m0); s0 += acc[nt][1];
                acc[nt][2] = __expf(acc[nt][2] - m1); s1 += acc[nt][2];
                acc[nt][3] = __expf(acc[nt][3] - m1); s1 += acc[nt][3];
            }
            s0 += __shfl_xor_sync(0xffffffffu, s0, 1);
            s0 += __shfl_xor_sync(0xffffffffu, s0, 2);
            s1 += __shfl_xor_sync(0xffffffffu, s1, 1);
            s1 += __shfl_xor_sync(0xffffffffu, s1, 2);
            float inv0 = 1.0f / s0, inv1 = 1.0f / s1;

            const __half* gb = g_gateh + (size_t)blk * 32768 + (size_t)head * 4096;
            float* Scm = &smf[SC_OFF + half * 4352];
            #pragma unroll
            for (int nt = 0; nt < 8; nt++) {
                int col = nt * 8 + ec;
                float2 g0 = __half22float2(*(const __half2*)(gb + r0 * 64 + col));
                float2 g1 = __half22float2(*(const __half2*)(gb + (r0 + 8) * 64 + col));
                float2 p0, p1;
                p0.x = acc[nt][0] * inv0 + g0.x;
                p0.y = acc[nt][1] * inv0 + g0.y;
                p1.x = acc[nt][2] * inv1 + g1.x;
                p1.y = acc[nt][3] * inv1 + g1.y;
                *(float2*)&Scm[r0 * 68 + col] = p0;
                *(float2*)&Scm[(r0 + 8) * 68 + col] = p1;
            }
        }
        __syncwarp();

        // ---- PV (2-term: P split, V plain tf32): rows [wg*16,+16) x 32 dims ----
        {
            uint32_t sP = sbase + (SC_OFF + half * 4352) * 4;
            uint32_t sV = sbase + (VT_OFF + half * 2176) * 4;
            uint32_t aAddr = sP + (uint32_t)((wg * 16 + a7) * 272 + ahi16);
            uint32_t bAddr = sV + (uint32_t)(b7 * 272 + bhi16);

            float pacc[4][4];
            #pragma unroll
            for (int nt = 0; nt < 4; nt++)
                #pragma unroll
                for (int t = 0; t < 4; t++) pacc[nt][t] = 0.0f;

            #pragma unroll
            for (int ks = 0; ks < 8; ks++) {
                uint32_t a[4], ah[4], al[4];
                ldsm4(a[0], a[1], a[2], a[3], aAddr + ks * 32);
                #pragma unroll
                for (int t = 0; t < 4; t++) split_tf32(a[t], ah[t], al[t]);
                uint32_t bh[2][4];
                #pragma unroll
                for (int p = 0; p < 2; p++)
                    ldsm4(bh[p][0], bh[p][1], bh[p][2], bh[p][3],
                          bAddr + (uint32_t)(p * 16 * 272) + ks * 32);
                #pragma unroll
                for (int nt = 0; nt < 4; nt++) {
                    int p = nt >> 1, i0 = (nt & 1) * 2;
                    mma_tf32(pacc[nt][0], pacc[nt][1], pacc[nt][2], pacc[nt][3],
                             ah[0], ah[1], ah[2], ah[3], bh[p][i0], bh[p][i0 + 1]);
                    mma_tf32(pacc[nt][0], pacc[nt][1], pacc[nt][2], pacc[nt][3],
                             al[0], al[1], al[2], al[3], bh[p][i0], bh[p][i0 + 1]);
                }
            }

            float* og0 = g_xm + (size_t)(t0 + r0) * 256 + head * 32;
            float* og1 = g_xm + (size_t)(t0 + r0 + 8) * 256 + head * 32;
            #pragma unroll
            for (int nt = 0; nt < 4; nt++) {
                int col = nt * 8 + ec;
                *(float2*)&og0[col] = make_float2(to_tf32f(pacc[nt][0]),
                                                  to_tf32f(pacc[nt][1]));
                *(float2*)&og1[col] = make_float2(to_tf32f(pacc[nt][2]),
                                                  to_tf32f(pacc[nt][3]));
            }
        }
    }
}

// ---------------- launch ----------------
extern "C" void kernel_launch(void* const* d_in, const int* in_sizes, int n_in,
                              void* d_out, int out_size)
{
    const float* x      = (const float*)d_in[0];
    const float* amask  = (const float*)d_in[1];
    const float* efeat  = (const float*)d_in[2];
    const float* qkv_w  = (const float*)d_in[3];
    const float* qkv_b  = (const float*)d_in[4];
    const float* proj_w = (const float*)d_in[5];
    const float* proj_b = (const float*)d_in[6];
    const float* eg_w1  = (const float*)d_in[7];
    const float* eg_b1  = (const float*)d_in[8];
    const float* eg_w2  = (const float*)d_in[9];
    const float* eg_b2  = (const float*)d_in[10];
    float* out = (float*)d_out;

    void* p_xc = nullptr; void* p_wc = nullptr;
    void* p_xm = nullptr; void* p_bias = nullptr;
    cudaGetSymbolAddress(&p_xc, g_xc);
    cudaGetSymbolAddress(&p_wc, g_wc);
    cudaGetSymbolAddress(&p_xm, g_xm);
    cudaGetSymbolAddress(&p_bias, g_bias);
    float* xc = (float*)p_xc;
    float* wc = (float*)p_wc;

    cudaFuncSetAttribute(attn_mma,
                         cudaFuncAttributeMaxDynamicSharedMemorySize, ATTN_SMEM);
    cudaFuncSetAttribute(gemm_cp,
                         cudaFuncAttributeMaxDynamicSharedMemorySize, GEMM_SMEM);
    cudaFuncSetAttribute(gemm_qkv,
                         cudaFuncAttributeMaxDynamicSharedMemorySize, GEMM_SMEM);

    // 0) merged tf32 pre-round (x | qkv_w | proj_w)
    cvt_all_k<<<(N4ALL + 255) / 256, 256>>>(
        (const float4*)x, (const float4*)qkv_w, (const float4*)proj_w,
        (float4*)xc, (float4*)wc);

    // 1) QKV projection -> g_q / g_k / g_v
    gemm_qkv<<<dim3(768 / 128, NTOK / 128), 256, GEMM_SMEM>>>(xc, wc, qkv_b);

    // 2) edge gate + bias matrix (compacted)
    gate_kernel<<<NBLK, 256>>>(amask, efeat, eg_w1, eg_b1, eg_w2, eg_b2);

    // 3) block attention (2-term QK, cp.async staging; profiled slot)
    attn_mma<<<NBLK, 256, ATTN_SMEM>>>((const float*)p_bias);

    // 4) output projection
    gemm_cp<<<dim3(CC / 128, NTOK / 128), 256, GEMM_SMEM>>>(
        (const float*)p_xm, wc + 768 * CC, proj_b, out, CC);
}